// round 8
// baseline (speedup 1.0000x reference)
#include <cuda_runtime.h>
#include <cuda_bf16.h>
#include <math.h>

// Problem dims (fixed for this dataset instance)
#define B_ 32
#define N_ 1024
#define C_ 64
#define D_ 512
#define K_ 20
#define LOG2PI 1.8378770664093453f
#define LOG2E 1.4426950408889634f
#define LN2F 0.6931471805599453f

// Scratch (allocation-free rule: __device__ globals)
__device__ float d_emission[B_ * N_ * C_];   // log2-domain emission (8MB, L2-resident)
__device__ float d_meansT[D_ * C_];
__device__ float d_invvar[D_];
__device__ float d_m2[C_];
__device__ float d_const;
__device__ float d_P[C_ * C_];               // exp(log_softmax(masked trans, axis=0))
__device__ float d_initlp[C_];               // log2 units
__device__ float d_lentab[K_ * C_];          // [duration-1][c], log2 units

__device__ __forceinline__ float ex2(float x) {
  float r; asm("ex2.approx.f32 %0, %1;" : "=f"(r) : "f"(x)); return r;
}
__device__ __forceinline__ float lg2(float x) {
  float r; asm("lg2.approx.f32 %0, %1;" : "=f"(r) : "f"(x)); return r;
}

// ---------------------------------------------------------------------------
// Small parameter transforms (single CTA)
// ---------------------------------------------------------------------------
__global__ void __launch_bounds__(256) prep_kernel(
    const float* __restrict__ means, const float* __restrict__ cov,
    const float* __restrict__ tl, const float* __restrict__ il,
    const float* __restrict__ plr) {
  int tid = threadIdx.x;
  __shared__ float red[256];
  __shared__ float sme[64 * 65];
  __shared__ float invs[64];

  float lsum = 0.f;
  for (int d = tid; d < D_; d += 256) {
    float var = cov[d * D_ + d];
    d_invvar[d] = 1.0f / var;
    lsum += logf(var);
  }
  red[tid] = lsum;
  __syncthreads();
  for (int o = 128; o > 0; o >>= 1) {
    if (tid < o) red[tid] += red[tid + o];
    __syncthreads();
  }
  if (tid == 0) d_const = -0.5f * (red[0] + (float)D_ * LOG2PI);

  {
    int w = tid >> 5, ln = tid & 31;
    for (int i = 0; i < 8; i++) {
      int cc = w + 8 * i;
      float s = 0.f;
      for (int j = ln; j < D_; j += 32) {
        float mm = means[cc * D_ + j];
        s += mm * mm * d_invvar[j];
      }
      for (int o = 16; o > 0; o >>= 1) s += __shfl_xor_sync(0xffffffffu, s, o);
      if (ln == 0) d_m2[cc] = s;
    }
  }

  for (int idx = tid; idx < 64 * 64; idx += 256) {
    int i = idx >> 6, j = idx & 63;
    sme[i * 65 + j] = (i == j) ? 0.f : expf(tl[i * 64 + j]);
  }
  __syncthreads();
  if (tid < 64) {
    float s = 0.f;
    for (int i = 0; i < 64; i++) s += sme[i * 65 + tid];
    invs[tid] = 1.0f / s;
  }
  __syncthreads();
  for (int idx = tid; idx < 64 * 64; idx += 256) {
    int i = idx >> 6, j = idx & 63;
    d_P[idx] = sme[i * 65 + j] * invs[j];
  }

  if (tid == 0) {
    float mx = -3e38f;
    for (int cc = 0; cc < 64; cc++) mx = fmaxf(mx, il[cc]);
    float s = 0.f;
    for (int cc = 0; cc < 64; cc++) s += expf(il[cc] - mx);
    float l = mx + logf(s);
    for (int cc = 0; cc < 64; cc++) d_initlp[cc] = (il[cc] - l) * LOG2E;
  }

  for (int idx = tid; idx < K_ * 64; idx += 256) {
    int dd = idx >> 6, cc = idx & 63;
    float lr = plr[cc];
    d_lentab[idx] = LOG2E * ((float)(dd + 1) * lr - expf(lr) - lgammaf((float)(dd + 2)));
  }
}

// ---------------------------------------------------------------------------
// Parallel transpose: meansT[d][c] = means[c][d] / var[d]
// ---------------------------------------------------------------------------
__global__ void __launch_bounds__(256) transpose_kernel(const float* __restrict__ means,
                                                        const float* __restrict__ cov) {
  __shared__ float tile[32][33];
  int d0 = blockIdx.x * 32, c0 = blockIdx.y * 32;
  int tx = threadIdx.x & 31, ty = threadIdx.x >> 5;
#pragma unroll
  for (int k = 0; k < 4; k++) {
    int cc = c0 + ty + 8 * k;
    tile[ty + 8 * k][tx] = means[cc * D_ + d0 + tx];
  }
  __syncthreads();
#pragma unroll
  for (int k = 0; k < 4; k++) {
    int dd = d0 + ty + 8 * k;
    float iv = 1.0f / cov[dd * D_ + dd];
    d_meansT[dd * C_ + c0 + tx] = tile[tx][ty + 8 * k] * iv;
  }
}

// ---------------------------------------------------------------------------
// Emission GEMM (log2-domain output)
// ---------------------------------------------------------------------------
__global__ void __launch_bounds__(256) emission_kernel(const float* __restrict__ feat) {
  __shared__ float fs[128][33];
  __shared__ float4 ms4[32][17];
  __shared__ float ivs[32];

  int tid = threadIdx.x;
  int r0 = blockIdx.x * 128;
  int cg = tid & 15;
  int rg = tid >> 4;

  float acc[8][4];
  float xacc[8];
#pragma unroll
  for (int i = 0; i < 8; i++) {
    xacc[i] = 0.f;
#pragma unroll
    for (int j = 0; j < 4; j++) acc[i][j] = 0.f;
  }

  for (int k0 = 0; k0 < D_; k0 += 32) {
#pragma unroll
    for (int ii = 0; ii < 16; ii++) {
      int idx = tid + 256 * ii;
      int row = idx >> 5, col = idx & 31;
      fs[row][col] = feat[(r0 + row) * D_ + k0 + col];
    }
#pragma unroll
    for (int ii = 0; ii < 2; ii++) {
      int idx = tid + 256 * ii;
      int k = idx >> 4, c4 = idx & 15;
      ms4[k][c4] = ((const float4*)(d_meansT + (k0 + k) * C_))[c4];
    }
    if (tid < 32) ivs[tid] = d_invvar[k0 + tid];
    __syncthreads();

#pragma unroll
    for (int k = 0; k < 32; k++) {
      float4 bv = ms4[k][cg];
      float iv = ivs[k];
#pragma unroll
      for (int i = 0; i < 8; i++) {
        float a = fs[rg * 8 + i][k];
        acc[i][0] = fmaf(a, bv.x, acc[i][0]);
        acc[i][1] = fmaf(a, bv.y, acc[i][1]);
        acc[i][2] = fmaf(a, bv.z, acc[i][2]);
        acc[i][3] = fmaf(a, bv.w, acc[i][3]);
        xacc[i] = fmaf(a * a, iv, xacc[i]);
      }
    }
    __syncthreads();
  }

  float cst = d_const;
  float4 m2v = ((const float4*)d_m2)[cg];
#pragma unroll
  for (int i = 0; i < 8; i++) {
    int row = r0 + rg * 8 + i;
    float base = cst - 0.5f * xacc[i];
    float4 o;
    o.x = LOG2E * (acc[i][0] - 0.5f * m2v.x + base);
    o.y = LOG2E * (acc[i][1] - 0.5f * m2v.y + base);
    o.z = LOG2E * (acc[i][2] - 0.5f * m2v.z + base);
    o.w = LOG2E * (acc[i][3] - 0.5f * m2v.w + base);
    ((float4*)(d_emission + row * C_))[cg] = o;
  }
}

// ---------------------------------------------------------------------------
// Semi-Markov scan v6: SINGLE WARP per batch. Lane l owns states (2l, 2l+1),
// everything bf16x2-packed: 20-deep linear duration ring (HFMA2 dot with
// L = 2^len), full-row matvec (64 HFMA2, 8 chains, broadcast LDS.128 of e).
// No block barriers — one __syncwarp per step. Delay-2 m-relay via 1 shfl.
// ---------------------------------------------------------------------------
__global__ void __launch_bounds__(32, 1) scan_kernel(const int* __restrict__ lengths,
                                                     float* __restrict__ out) {
  const int b = blockIdx.x;
  const int lane = threadIdx.x;
  const int i0 = 2 * lane, i1 = 2 * lane + 1;

  __shared__ __align__(16) unsigned int e_sm[2][32];   // bf16x2 per lane, double-buffered

  // transition rows, packed along j: P2_0[s] = (P[i0][2s], P[i0][2s+1])
  __nv_bfloat162 P2_0[32], P2_1[32];
#pragma unroll
  for (int s = 0; s < 32; s++) {
    P2_0[s] = __floats2bfloat162_rn(d_P[i0 * 64 + 2 * s], d_P[i0 * 64 + 2 * s + 1]);
    P2_1[s] = __floats2bfloat162_rn(d_P[i1 * 64 + 2 * s], d_P[i1 * 64 + 2 * s + 1]);
  }

  // linear duration weights L2[k] = 2^len(dur=k+1) for the 2 states
  __nv_bfloat162 L2[20];
#pragma unroll
  for (int k = 0; k < 20; k++)
    L2[k] = __floats2bfloat162_rn(ex2(d_lentab[k * 64 + i0]), ex2(d_lentab[k * 64 + i1]));

  // ring W2: at phase P, duration d entry lives at index (3-P)+d ; insert at 3-P
  __nv_bfloat162 W2[24];
  const __nv_bfloat162 zero2 = __floats2bfloat162_rn(0.f, 0.f);
#pragma unroll
  for (int i = 0; i < 24; i++) W2[i] = zero2;
  W2[4] = __floats2bfloat162_rn(ex2(d_initlp[i0]), ex2(d_initlp[i1]));   // d=1 at phase 0

  const int len_b = lengths[b];
  const float* em = d_emission + b * (N_ * C_);

  float2 emr_a = *(const float2*)(em + i0);            // row 0 (= emission at t=1)
  float2 emr_b = *(const float2*)(em + 64 + i0);       // row 1
  float2 emr_c = *(const float2*)(em + 128 + i0);      // row 2

  float m = em[0] + d_initlp[0] + d_lentab[0];         // exact alpha_1[0] (log2)
  float m_prev = 0.f;
  float beta0_prev = d_initlp[0];                      // beta_0[0] (log2)

#define STEP(P)                                                                  \
  {                                                                              \
    const int t = tb + (P) + 1;                                                  \
    const int BUF = t & 1;                                                       \
    float2 emNew = make_float2(0.f, 0.f);                                        \
    if (t + 2 < N_) emNew = *(const float2*)(em + (t + 2) * 64 + i0);            \
    float dm = m - m_prev;                                                       \
    __nv_bfloat162 sc2 =                                                         \
        __floats2bfloat162_rn(ex2(emr_a.x - dm), ex2(emr_a.y - dm));             \
    /* duration dot: S = sum_d W_d * L_d  (two 10-deep HFMA2 chains) */          \
    __nv_bfloat162 sa = __hmul2(W2[4 - (P)], L2[0]);                             \
    __nv_bfloat162 sb = __hmul2(W2[5 - (P)], L2[1]);                             \
    _Pragma("unroll")                                                            \
    for (int k = 2; k < 20; k += 2) {                                            \
      sa = __hfma2(W2[4 - (P) + k], L2[k], sa);                                  \
      sb = __hfma2(W2[5 - (P) + k], L2[k + 1], sb);                              \
    }                                                                            \
    __nv_bfloat162 S2 = __hadd2(sa, sb);                                         \
    __nv_bfloat162 e2 = __hmul2(S2, sc2);      /* = 2^(alpha_t - m_t) */         \
    e_sm[BUF][lane] = *(unsigned int*)&e2;                                       \
    /* rescale surviving 19 ring entries (d=1..19 -> d=2..20) */                 \
    _Pragma("unroll")                                                            \
    for (int k = 0; k < 19; k++) W2[4 - (P) + k] = __hmul2(W2[4 - (P) + k], sc2);\
    __syncwarp();                                                                \
    /* matvec: acc_i = sum_j P[i][j] e_j ; broadcast LDS.128, 8 acc chains */    \
    const uint4* Ev = (const uint4*)&e_sm[BUF][0];                               \
    __nv_bfloat162 a00, a01, a02, a03, a10, a11, a12, a13;                       \
    {                                                                            \
      uint4 u = Ev[0];                                                           \
      const __nv_bfloat162* ep = (const __nv_bfloat162*)&u;                      \
      a00 = __hmul2(P2_0[0], ep[0]); a10 = __hmul2(P2_1[0], ep[0]);              \
      a01 = __hmul2(P2_0[1], ep[1]); a11 = __hmul2(P2_1[1], ep[1]);              \
      a02 = __hmul2(P2_0[2], ep[2]); a12 = __hmul2(P2_1[2], ep[2]);              \
      a03 = __hmul2(P2_0[3], ep[3]); a13 = __hmul2(P2_1[3], ep[3]);              \
    }                                                                            \
    _Pragma("unroll")                                                            \
    for (int q = 1; q < 8; q++) {                                                \
      uint4 u = Ev[q];                                                           \
      const __nv_bfloat162* ep = (const __nv_bfloat162*)&u;                      \
      a00 = __hfma2(P2_0[4 * q + 0], ep[0], a00);                                \
      a10 = __hfma2(P2_1[4 * q + 0], ep[0], a10);                                \
      a01 = __hfma2(P2_0[4 * q + 1], ep[1], a01);                                \
      a11 = __hfma2(P2_1[4 * q + 1], ep[1], a11);                                \
      a02 = __hfma2(P2_0[4 * q + 2], ep[2], a02);                                \
      a12 = __hfma2(P2_1[4 * q + 2], ep[2], a12);                                \
      a03 = __hfma2(P2_0[4 * q + 3], ep[3], a03);                                \
      a13 = __hfma2(P2_1[4 * q + 3], ep[3], a13);                                \
    }                                                                            \
    __nv_bfloat162 am0 = __hadd2(__hadd2(a00, a01), __hadd2(a02, a03));          \
    __nv_bfloat162 am1 = __hadd2(__hadd2(a10, a11), __hadd2(a12, a13));          \
    float2 f0 = __bfloat1622float2(am0);                                         \
    float2 f1 = __bfloat1622float2(am1);                                         \
    float acc0f = f0.x + f0.y;                                                   \
    float acc1f = f1.x + f1.y;                                                   \
    W2[3 - (P)] = __floats2bfloat162_rn(acc0f, acc1f);   /* new d=1 entry */     \
    /* m relay (delay-2): m_{t+1} = beta_{t-1}[0] + em_t[0] + em_{t+1}[0] */     \
    float mval = beta0_prev + emr_a.x + emr_b.x;                                 \
    float m_next = __shfl_sync(0xffffffffu, mval, 0);                            \
    beta0_prev = m + lg2(fmaxf(acc0f, 1e-30f));    /* beta_t[0] (lane0 valid) */ \
    if (t == len_b) {                                                            \
      float2 ef = __bfloat1622float2(e2);                                        \
      float se = ef.x + ef.y;                                                    \
      for (int o = 16; o > 0; o >>= 1) se += __shfl_xor_sync(0xffffffffu, se, o);\
      if (lane == 0) out[b] = (m + lg2(se)) * LN2F;                              \
    }                                                                            \
    m_prev = m; m = m_next;                                                      \
    emr_a = emr_b; emr_b = emr_c; emr_c = emNew;                                 \
  }

  for (int tb = 0; tb < N_; tb += 4) {
    STEP(0)
    STEP(1)
    STEP(2)
    STEP(3)
#pragma unroll
    for (int i = 23; i >= 4; i--) W2[i] = W2[i - 4];
  }
#undef STEP
}

// ---------------------------------------------------------------------------
extern "C" void kernel_launch(void* const* d_in, const int* in_sizes, int n_in,
                              void* d_out, int out_size) {
  const float* feat    = (const float*)d_in[0];
  const int*   lengths = (const int*)d_in[1];
  const float* means   = (const float*)d_in[2];
  const float* cov     = (const float*)d_in[3];
  const float* tl      = (const float*)d_in[4];
  const float* il      = (const float*)d_in[5];
  const float* plr     = (const float*)d_in[6];
  float* out = (float*)d_out;

  prep_kernel<<<1, 256>>>(means, cov, tl, il, plr);
  transpose_kernel<<<dim3(16, 2), 256>>>(means, cov);
  emission_kernel<<<(B_ * N_) / 128, 256>>>(feat);
  scan_kernel<<<B_, 32>>>(lengths, out);
}

// round 10
// speedup vs baseline: 1.1387x; 1.1387x over previous
#include <cuda_runtime.h>
#include <cuda_bf16.h>
#include <math.h>

// Problem dims (fixed for this dataset instance)
#define B_ 32
#define N_ 1024
#define C_ 64
#define D_ 512
#define K_ 20
#define LOG2PI 1.8378770664093453f
#define LOG2E 1.4426950408889634f
#define LN2F 0.6931471805599453f

// Scratch (allocation-free rule: __device__ globals)
__device__ float d_emission[B_ * N_ * C_];   // log2-domain emission (8MB, L2-resident)
__device__ float d_meansT[D_ * C_];
__device__ float d_invvar[D_];
__device__ float d_m2[C_];
__device__ float d_const;
__device__ float d_P[C_ * C_];               // exp(log_softmax(masked trans, axis=0))
__device__ float d_initlp[C_];               // log2 units
__device__ float d_lentab[K_ * C_];          // [duration-1][c], log2 units

__device__ __forceinline__ float ex2(float x) {
  float r; asm("ex2.approx.f32 %0, %1;" : "=f"(r) : "f"(x)); return r;
}
__device__ __forceinline__ float lg2(float x) {
  float r; asm("lg2.approx.f32 %0, %1;" : "=f"(r) : "f"(x)); return r;
}

// ---------------------------------------------------------------------------
// Small parameter transforms (single CTA)
// ---------------------------------------------------------------------------
__global__ void __launch_bounds__(256) prep_kernel(
    const float* __restrict__ means, const float* __restrict__ cov,
    const float* __restrict__ tl, const float* __restrict__ il,
    const float* __restrict__ plr) {
  int tid = threadIdx.x;
  __shared__ float red[256];
  __shared__ float sme[64 * 65];
  __shared__ float invs[64];

  float lsum = 0.f;
  for (int d = tid; d < D_; d += 256) {
    float var = cov[d * D_ + d];
    d_invvar[d] = 1.0f / var;
    lsum += logf(var);
  }
  red[tid] = lsum;
  __syncthreads();
  for (int o = 128; o > 0; o >>= 1) {
    if (tid < o) red[tid] += red[tid + o];
    __syncthreads();
  }
  if (tid == 0) d_const = -0.5f * (red[0] + (float)D_ * LOG2PI);

  {
    int w = tid >> 5, ln = tid & 31;
    for (int i = 0; i < 8; i++) {
      int cc = w + 8 * i;
      float s = 0.f;
      for (int j = ln; j < D_; j += 32) {
        float mm = means[cc * D_ + j];
        s += mm * mm * d_invvar[j];
      }
      for (int o = 16; o > 0; o >>= 1) s += __shfl_xor_sync(0xffffffffu, s, o);
      if (ln == 0) d_m2[cc] = s;
    }
  }

  for (int idx = tid; idx < 64 * 64; idx += 256) {
    int i = idx >> 6, j = idx & 63;
    sme[i * 65 + j] = (i == j) ? 0.f : expf(tl[i * 64 + j]);
  }
  __syncthreads();
  if (tid < 64) {
    float s = 0.f;
    for (int i = 0; i < 64; i++) s += sme[i * 65 + tid];
    invs[tid] = 1.0f / s;
  }
  __syncthreads();
  for (int idx = tid; idx < 64 * 64; idx += 256) {
    int i = idx >> 6, j = idx & 63;
    d_P[idx] = sme[i * 65 + j] * invs[j];
  }

  if (tid == 0) {
    float mx = -3e38f;
    for (int cc = 0; cc < 64; cc++) mx = fmaxf(mx, il[cc]);
    float s = 0.f;
    for (int cc = 0; cc < 64; cc++) s += expf(il[cc] - mx);
    float l = mx + logf(s);
    for (int cc = 0; cc < 64; cc++) d_initlp[cc] = (il[cc] - l) * LOG2E;
  }

  for (int idx = tid; idx < K_ * 64; idx += 256) {
    int dd = idx >> 6, cc = idx & 63;
    float lr = plr[cc];
    d_lentab[idx] = LOG2E * ((float)(dd + 1) * lr - expf(lr) - lgammaf((float)(dd + 2)));
  }
}

// ---------------------------------------------------------------------------
// Parallel transpose: meansT[d][c] = means[c][d] / var[d]
// ---------------------------------------------------------------------------
__global__ void __launch_bounds__(256) transpose_kernel(const float* __restrict__ means,
                                                        const float* __restrict__ cov) {
  __shared__ float tile[32][33];
  int d0 = blockIdx.x * 32, c0 = blockIdx.y * 32;
  int tx = threadIdx.x & 31, ty = threadIdx.x >> 5;
#pragma unroll
  for (int k = 0; k < 4; k++) {
    int cc = c0 + ty + 8 * k;
    tile[ty + 8 * k][tx] = means[cc * D_ + d0 + tx];
  }
  __syncthreads();
#pragma unroll
  for (int k = 0; k < 4; k++) {
    int dd = d0 + ty + 8 * k;
    float iv = 1.0f / cov[dd * D_ + dd];
    d_meansT[dd * C_ + c0 + tx] = tile[tx][ty + 8 * k] * iv;
  }
}

// ---------------------------------------------------------------------------
// Emission GEMM (log2-domain output)
// ---------------------------------------------------------------------------
__global__ void __launch_bounds__(256) emission_kernel(const float* __restrict__ feat) {
  __shared__ float fs[128][33];
  __shared__ float4 ms4[32][17];
  __shared__ float ivs[32];

  int tid = threadIdx.x;
  int r0 = blockIdx.x * 128;
  int cg = tid & 15;
  int rg = tid >> 4;

  float acc[8][4];
  float xacc[8];
#pragma unroll
  for (int i = 0; i < 8; i++) {
    xacc[i] = 0.f;
#pragma unroll
    for (int j = 0; j < 4; j++) acc[i][j] = 0.f;
  }

  for (int k0 = 0; k0 < D_; k0 += 32) {
#pragma unroll
    for (int ii = 0; ii < 16; ii++) {
      int idx = tid + 256 * ii;
      int row = idx >> 5, col = idx & 31;
      fs[row][col] = feat[(r0 + row) * D_ + k0 + col];
    }
#pragma unroll
    for (int ii = 0; ii < 2; ii++) {
      int idx = tid + 256 * ii;
      int k = idx >> 4, c4 = idx & 15;
      ms4[k][c4] = ((const float4*)(d_meansT + (k0 + k) * C_))[c4];
    }
    if (tid < 32) ivs[tid] = d_invvar[k0 + tid];
    __syncthreads();

#pragma unroll
    for (int k = 0; k < 32; k++) {
      float4 bv = ms4[k][cg];
      float iv = ivs[k];
#pragma unroll
      for (int i = 0; i < 8; i++) {
        float a = fs[rg * 8 + i][k];
        acc[i][0] = fmaf(a, bv.x, acc[i][0]);
        acc[i][1] = fmaf(a, bv.y, acc[i][1]);
        acc[i][2] = fmaf(a, bv.z, acc[i][2]);
        acc[i][3] = fmaf(a, bv.w, acc[i][3]);
        xacc[i] = fmaf(a * a, iv, xacc[i]);
      }
    }
    __syncthreads();
  }

  float cst = d_const;
  float4 m2v = ((const float4*)d_m2)[cg];
#pragma unroll
  for (int i = 0; i < 8; i++) {
    int row = r0 + rg * 8 + i;
    float base = cst - 0.5f * xacc[i];
    float4 o;
    o.x = LOG2E * (acc[i][0] - 0.5f * m2v.x + base);
    o.y = LOG2E * (acc[i][1] - 0.5f * m2v.y + base);
    o.z = LOG2E * (acc[i][2] - 0.5f * m2v.z + base);
    o.w = LOG2E * (acc[i][3] - 0.5f * m2v.w + base);
    ((float4*)(d_emission + row * C_))[cg] = o;
  }
}

// ---------------------------------------------------------------------------
// Semi-Markov scan v7: 64 threads (2 warps), ONE state per lane.
// - Lane c owns state c: full 20-duration linear ring + full matvec row.
//   => ZERO shfls in the steady loop; one __syncthreads (nw=2) per step.
// - Ring: fp32 scalars W1 (fresh = prev acc, exact) & W11, plus 9 bf16x2
//   pairs (d_i, d_{i+10}) for d=2..10/12..20. Shift = index rotation (x4 unroll).
// - Old-only partial dot precomputed; post-acc chain = 1 FFMA -> cvt -> STS.16.
// - m relay: lane0 writes m_{t+1} to smem pre-bar; all read post-bar.
// ---------------------------------------------------------------------------
__global__ void __launch_bounds__(64, 1) scan_kernel(const int* __restrict__ lengths,
                                                     float* __restrict__ out) {
  const int b = blockIdx.x;
  const int c = threadIdx.x;   // state 0..63

  __shared__ __align__(16) __nv_bfloat16 e_sm[2][64];
  __shared__ float m_sm[2];

  // transition row, packed along j
  __nv_bfloat162 P2[32];
#pragma unroll
  for (int s = 0; s < 32; s++)
    P2[s] = __floats2bfloat162_rn(d_P[c * 64 + 2 * s], d_P[c * 64 + 2 * s + 1]);

  // duration weights: Λ_d = 2^len_d. Scalars for d=1,11; pairs (Λ_i, Λ_{i+10}) i=2..10.
  const float L1f = ex2(d_lentab[0 * 64 + c]);
  const float L11f = ex2(d_lentab[10 * 64 + c]);
  __nv_bfloat162 L2[11];
#pragma unroll
  for (int i = 2; i <= 10; i++)
    L2[i] = __floats2bfloat162_rn(ex2(d_lentab[(i - 1) * 64 + c]),
                                  ex2(d_lentab[(i + 9) * 64 + c]));

  // ring: WP slots; at phase P, pair i (i=2..10) lives at WP[i+3-P]; fresh pair
  // created during phase P is stored at WP[4-P].
  __nv_bfloat162 WP[14];
  const __nv_bfloat162 z2 = __float2bfloat162_rn(0.f);
#pragma unroll
  for (int i = 0; i < 14; i++) WP[i] = z2;
  float acc = ex2(d_initlp[c]);   // W1 entering step 1 (exact: 2^{g_0})
  float W11 = 0.f;

  const int len_b = lengths[b];
  const float* em = d_emission + b * (N_ * C_);
  float emr_a = em[c];            // row 0 = em_1[c]
  float emr_b = em[64 + c];       // row 1
  float emr_c2 = em[128 + c];     // row 2

  float m = em[0] + d_initlp[0] + d_lentab[0];   // exact alpha_1[0] (log2)
  float m_prev = 0.f;
  float beta0_prev = d_initlp[0];                // beta_0[0] (lane0's value used)

#define STEP(P)                                                                  \
  {                                                                              \
    const int t = tb + (P) + 1;                                                  \
    const int BUF = t & 1;                                                       \
    float emNew = 0.f;                                                           \
    if (t + 2 < N_) emNew = em[(t + 2) * 64 + c];                                \
    float dm = m - m_prev;                                                       \
    float sc = ex2(emr_a - dm);     /* 2^{rho_t - rho_{t+1}} */                  \
    __nv_bfloat162 sc2 = __float2bfloat162_rn(sc);                               \
    /* old-only partial dot: pairs d=2..10 / 12..20, plus scalar d=11 */         \
    __nv_bfloat162 ha = __hmul2(WP[5 - (P)], L2[2]);                             \
    __nv_bfloat162 hb = __hmul2(WP[6 - (P)], L2[3]);                             \
    ha = __hfma2(WP[7 - (P)], L2[4], ha);                                        \
    hb = __hfma2(WP[8 - (P)], L2[5], hb);                                        \
    ha = __hfma2(WP[9 - (P)], L2[6], ha);                                        \
    hb = __hfma2(WP[10 - (P)], L2[7], hb);                                       \
    ha = __hfma2(WP[11 - (P)], L2[8], ha);                                       \
    hb = __hfma2(WP[12 - (P)], L2[9], hb);                                       \
    ha = __hfma2(WP[13 - (P)], L2[10], ha);                                      \
    ha = __hadd2(ha, hb);                                                        \
    float2 hf = __bfloat1622float2(ha);                                          \
    float partial = fmaf(W11, L11f, hf.x + hf.y);                                \
    float pe = partial * sc;                                                     \
    float Lsc = L1f * sc;                                                        \
    /* aging d10 -> d11 (value x sc), new pair (d2,d12) from W1,W11 */           \
    float W11n = __bfloat162float(WP[13 - (P)].x) * sc;                          \
    WP[4 - (P)] = __floats2bfloat162_rn(acc * sc, W11 * sc);                     \
    /* rescale old pairs to rho_{t+1} */                                         \
    _Pragma("unroll")                                                            \
    for (int i = 2; i <= 10; i++)                                                \
      WP[i + 3 - (P)] = __hmul2(WP[i + 3 - (P)], sc2);                           \
    /* e_t = 2^{alpha_t - m_t}: single FFMA after fresh acc */                   \
    float e = fmaf(acc, Lsc, pe);                                                \
    e_sm[BUF][c] = __float2bfloat16(e);                                          \
    float mval = beta0_prev + emr_a + emr_b;    /* m_{t+1} (lane0's is real) */  \
    if (c == 0) m_sm[BUF] = mval;                                                \
    __syncthreads();                                                             \
    /* matvec: acc_c = sum_j P[c][j] e_j ; 4 broadcast LDS.128, 8 chains */      \
    const uint4* Ev = (const uint4*)&e_sm[BUF][0];                               \
    uint4 u0 = Ev[0], u1 = Ev[1], u2 = Ev[2], u3 = Ev[3];                        \
    const __nv_bfloat162* e0 = (const __nv_bfloat162*)&u0;                       \
    const __nv_bfloat162* e1 = (const __nv_bfloat162*)&u1;                       \
    const __nv_bfloat162* e2p = (const __nv_bfloat162*)&u2;                      \
    const __nv_bfloat162* e3 = (const __nv_bfloat162*)&u3;                       \
    __nv_bfloat162 a0 = __hmul2(P2[0], e0[0]);                                   \
    __nv_bfloat162 a1 = __hmul2(P2[1], e0[1]);                                   \
    __nv_bfloat162 a2 = __hmul2(P2[2], e0[2]);                                   \
    __nv_bfloat162 a3 = __hmul2(P2[3], e0[3]);                                   \
    __nv_bfloat162 a4 = __hmul2(P2[4], e1[0]);                                   \
    __nv_bfloat162 a5 = __hmul2(P2[5], e1[1]);                                   \
    __nv_bfloat162 a6 = __hmul2(P2[6], e1[2]);                                   \
    __nv_bfloat162 a7 = __hmul2(P2[7], e1[3]);                                   \
    a0 = __hfma2(P2[8], e2p[0], a0);                                             \
    a1 = __hfma2(P2[9], e2p[1], a1);                                             \
    a2 = __hfma2(P2[10], e2p[2], a2);                                            \
    a3 = __hfma2(P2[11], e2p[3], a3);                                            \
    a4 = __hfma2(P2[12], e3[0], a4);                                             \
    a5 = __hfma2(P2[13], e3[1], a5);                                             \
    a6 = __hfma2(P2[14], e3[2], a6);                                             \
    a7 = __hfma2(P2[15], e3[3], a7);                                             \
    uint4 v0 = Ev[4], v1 = Ev[5], v2 = Ev[6], v3 = Ev[7];                        \
    const __nv_bfloat162* f0p = (const __nv_bfloat162*)&v0;                      \
    const __nv_bfloat162* f1p = (const __nv_bfloat162*)&v1;                      \
    const __nv_bfloat162* f2p = (const __nv_bfloat162*)&v2;                      \
    const __nv_bfloat162* f3p = (const __nv_bfloat162*)&v3;                      \
    a0 = __hfma2(P2[16], f0p[0], a0);                                            \
    a1 = __hfma2(P2[17], f0p[1], a1);                                            \
    a2 = __hfma2(P2[18], f0p[2], a2);                                            \
    a3 = __hfma2(P2[19], f0p[3], a3);                                            \
    a4 = __hfma2(P2[20], f1p[0], a4);                                            \
    a5 = __hfma2(P2[21], f1p[1], a5);                                            \
    a6 = __hfma2(P2[22], f1p[2], a6);                                            \
    a7 = __hfma2(P2[23], f1p[3], a7);                                            \
    a0 = __hfma2(P2[24], f2p[0], a0);                                            \
    a1 = __hfma2(P2[25], f2p[1], a1);                                            \
    a2 = __hfma2(P2[26], f2p[2], a2);                                            \
    a3 = __hfma2(P2[27], f2p[3], a3);                                            \
    a4 = __hfma2(P2[28], f3p[0], a4);                                            \
    a5 = __hfma2(P2[29], f3p[1], a5);                                            \
    a6 = __hfma2(P2[30], f3p[2], a6);                                            \
    a7 = __hfma2(P2[31], f3p[3], a7);                                            \
    a0 = __hadd2(a0, a1); a2 = __hadd2(a2, a3);                                  \
    a4 = __hadd2(a4, a5); a6 = __hadd2(a6, a7);                                  \
    a0 = __hadd2(a0, a2); a4 = __hadd2(a4, a6);                                  \
    a0 = __hadd2(a0, a4);                                                        \
    float2 af = __bfloat1622float2(a0);                                          \
    float accf = af.x + af.y;                                                    \
    float m_read = m_sm[BUF];                                                    \
    beta0_prev = m + lg2(fmaxf(accf, 1e-30f));                                   \
    if (t == len_b && c == 0) {                                                  \
      float se = 0.f;                                                            \
      for (int j = 0; j < 64; j++) se += __bfloat162float(e_sm[BUF][j]);         \
      out[b] = (m + lg2(se)) * LN2F;                                             \
    }                                                                            \
    W11 = W11n; acc = accf;                                                      \
    m_prev = m; m = m_read;                                                      \
    emr_a = emr_b; emr_b = emr_c2; emr_c2 = emNew;                               \
  }

  for (int tb = 0; tb < N_; tb += 4) {
    STEP(0)
    STEP(1)
    STEP(2)
    STEP(3)
    // restore group invariant: ring index rotation by 4
#pragma unroll
    for (int i = 13; i >= 5; i--) WP[i] = WP[i - 4];
  }
#undef STEP
}

// ---------------------------------------------------------------------------
extern "C" void kernel_launch(void* const* d_in, const int* in_sizes, int n_in,
                              void* d_out, int out_size) {
  const float* feat    = (const float*)d_in[0];
  const int*   lengths = (const int*)d_in[1];
  const float* means   = (const float*)d_in[2];
  const float* cov     = (const float*)d_in[3];
  const float* tl      = (const float*)d_in[4];
  const float* il      = (const float*)d_in[5];
  const float* plr     = (const float*)d_in[6];
  float* out = (float*)d_out;

  prep_kernel<<<1, 256>>>(means, cov, tl, il, plr);
  transpose_kernel<<<dim3(16, 2), 256>>>(means, cov);
  emission_kernel<<<(B_ * N_) / 128, 256>>>(feat);
  scan_kernel<<<B_, 64>>>(lengths, out);
}

// round 11
// speedup vs baseline: 1.2254x; 1.0761x over previous
#include <cuda_runtime.h>
#include <cuda_bf16.h>
#include <math.h>

// Problem dims (fixed for this dataset instance)
#define B_ 32
#define N_ 1024
#define C_ 64
#define D_ 512
#define K_ 20
#define LOG2PI 1.8378770664093453f
#define LOG2E 1.4426950408889634f
#define LN2F 0.6931471805599453f

// Scratch (allocation-free rule: __device__ globals)
__device__ float d_emission[B_ * N_ * C_];   // log2-domain emission (8MB, L2-resident)
__device__ float d_meansT[D_ * C_];
__device__ float d_invvar[D_];
__device__ float d_m2[C_];
__device__ float d_const;
__device__ float d_P[C_ * C_];               // exp(log_softmax(masked trans, axis=0))
__device__ float d_initlp[C_];               // log2 units
__device__ float d_lentab[K_ * C_];          // [duration-1][c], log2 units

__device__ __forceinline__ float ex2(float x) {
  float r; asm("ex2.approx.f32 %0, %1;" : "=f"(r) : "f"(x)); return r;
}
__device__ __forceinline__ float lg2(float x) {
  float r; asm("lg2.approx.f32 %0, %1;" : "=f"(r) : "f"(x)); return r;
}

// ---------------------------------------------------------------------------
// Small parameter transforms (single CTA)
// ---------------------------------------------------------------------------
__global__ void __launch_bounds__(256) prep_kernel(
    const float* __restrict__ means, const float* __restrict__ cov,
    const float* __restrict__ tl, const float* __restrict__ il,
    const float* __restrict__ plr) {
  int tid = threadIdx.x;
  __shared__ float red[256];
  __shared__ float sme[64 * 65];
  __shared__ float invs[64];

  float lsum = 0.f;
  for (int d = tid; d < D_; d += 256) {
    float var = cov[d * D_ + d];
    d_invvar[d] = 1.0f / var;
    lsum += logf(var);
  }
  red[tid] = lsum;
  __syncthreads();
  for (int o = 128; o > 0; o >>= 1) {
    if (tid < o) red[tid] += red[tid + o];
    __syncthreads();
  }
  if (tid == 0) d_const = -0.5f * (red[0] + (float)D_ * LOG2PI);

  {
    int w = tid >> 5, ln = tid & 31;
    for (int i = 0; i < 8; i++) {
      int cc = w + 8 * i;
      float s = 0.f;
      for (int j = ln; j < D_; j += 32) {
        float mm = means[cc * D_ + j];
        s += mm * mm * d_invvar[j];
      }
      for (int o = 16; o > 0; o >>= 1) s += __shfl_xor_sync(0xffffffffu, s, o);
      if (ln == 0) d_m2[cc] = s;
    }
  }

  for (int idx = tid; idx < 64 * 64; idx += 256) {
    int i = idx >> 6, j = idx & 63;
    sme[i * 65 + j] = (i == j) ? 0.f : expf(tl[i * 64 + j]);
  }
  __syncthreads();
  if (tid < 64) {
    float s = 0.f;
    for (int i = 0; i < 64; i++) s += sme[i * 65 + tid];
    invs[tid] = 1.0f / s;
  }
  __syncthreads();
  for (int idx = tid; idx < 64 * 64; idx += 256) {
    int i = idx >> 6, j = idx & 63;
    d_P[idx] = sme[i * 65 + j] * invs[j];
  }

  if (tid == 0) {
    float mx = -3e38f;
    for (int cc = 0; cc < 64; cc++) mx = fmaxf(mx, il[cc]);
    float s = 0.f;
    for (int cc = 0; cc < 64; cc++) s += expf(il[cc] - mx);
    float l = mx + logf(s);
    for (int cc = 0; cc < 64; cc++) d_initlp[cc] = (il[cc] - l) * LOG2E;
  }

  for (int idx = tid; idx < K_ * 64; idx += 256) {
    int dd = idx >> 6, cc = idx & 63;
    float lr = plr[cc];
    d_lentab[idx] = LOG2E * ((float)(dd + 1) * lr - expf(lr) - lgammaf((float)(dd + 2)));
  }
}

// ---------------------------------------------------------------------------
// Parallel transpose: meansT[d][c] = means[c][d] / var[d]
// ---------------------------------------------------------------------------
__global__ void __launch_bounds__(256) transpose_kernel(const float* __restrict__ means,
                                                        const float* __restrict__ cov) {
  __shared__ float tile[32][33];
  int d0 = blockIdx.x * 32, c0 = blockIdx.y * 32;
  int tx = threadIdx.x & 31, ty = threadIdx.x >> 5;
#pragma unroll
  for (int k = 0; k < 4; k++) {
    int cc = c0 + ty + 8 * k;
    tile[ty + 8 * k][tx] = means[cc * D_ + d0 + tx];
  }
  __syncthreads();
#pragma unroll
  for (int k = 0; k < 4; k++) {
    int dd = d0 + ty + 8 * k;
    float iv = 1.0f / cov[dd * D_ + dd];
    d_meansT[dd * C_ + c0 + tx] = tile[tx][ty + 8 * k] * iv;
  }
}

// ---------------------------------------------------------------------------
// Emission GEMM (log2-domain output)
// ---------------------------------------------------------------------------
__global__ void __launch_bounds__(256) emission_kernel(const float* __restrict__ feat) {
  __shared__ float fs[128][33];
  __shared__ float4 ms4[32][17];
  __shared__ float ivs[32];

  int tid = threadIdx.x;
  int r0 = blockIdx.x * 128;
  int cg = tid & 15;
  int rg = tid >> 4;

  float acc[8][4];
  float xacc[8];
#pragma unroll
  for (int i = 0; i < 8; i++) {
    xacc[i] = 0.f;
#pragma unroll
    for (int j = 0; j < 4; j++) acc[i][j] = 0.f;
  }

  for (int k0 = 0; k0 < D_; k0 += 32) {
#pragma unroll
    for (int ii = 0; ii < 16; ii++) {
      int idx = tid + 256 * ii;
      int row = idx >> 5, col = idx & 31;
      fs[row][col] = feat[(r0 + row) * D_ + k0 + col];
    }
#pragma unroll
    for (int ii = 0; ii < 2; ii++) {
      int idx = tid + 256 * ii;
      int k = idx >> 4, c4 = idx & 15;
      ms4[k][c4] = ((const float4*)(d_meansT + (k0 + k) * C_))[c4];
    }
    if (tid < 32) ivs[tid] = d_invvar[k0 + tid];
    __syncthreads();

#pragma unroll
    for (int k = 0; k < 32; k++) {
      float4 bv = ms4[k][cg];
      float iv = ivs[k];
#pragma unroll
      for (int i = 0; i < 8; i++) {
        float a = fs[rg * 8 + i][k];
        acc[i][0] = fmaf(a, bv.x, acc[i][0]);
        acc[i][1] = fmaf(a, bv.y, acc[i][1]);
        acc[i][2] = fmaf(a, bv.z, acc[i][2]);
        acc[i][3] = fmaf(a, bv.w, acc[i][3]);
        xacc[i] = fmaf(a * a, iv, xacc[i]);
      }
    }
    __syncthreads();
  }

  float cst = d_const;
  float4 m2v = ((const float4*)d_m2)[cg];
#pragma unroll
  for (int i = 0; i < 8; i++) {
    int row = r0 + rg * 8 + i;
    float base = cst - 0.5f * xacc[i];
    float4 o;
    o.x = LOG2E * (acc[i][0] - 0.5f * m2v.x + base);
    o.y = LOG2E * (acc[i][1] - 0.5f * m2v.y + base);
    o.z = LOG2E * (acc[i][2] - 0.5f * m2v.z + base);
    o.w = LOG2E * (acc[i][3] - 0.5f * m2v.w + base);
    ((float4*)(d_emission + row * C_))[cg] = o;
  }
}

// ---------------------------------------------------------------------------
// Semi-Markov scan v8: 64 threads (2 warps), 1 state/lane, ALL-bf16 chain.
// No F2FP conversions on the serial loop: acc, W11, partial dot, e are bf16
// scalars; sc's cvt is input-side (off-chain). Branchless steps (clamped
// prefetch, predicated len_b capture); final reduction after the loop.
// ---------------------------------------------------------------------------
__global__ void __launch_bounds__(64, 1) scan_kernel(const int* __restrict__ lengths,
                                                     float* __restrict__ out) {
  const int b = blockIdx.x;
  const int c = threadIdx.x;   // state 0..63

  __shared__ __align__(16) __nv_bfloat16 e_sm[2][64];
  __shared__ float m_sm[2];
  __shared__ float red_sm[2];

  // transition row, packed along j
  __nv_bfloat162 P2[32];
#pragma unroll
  for (int s = 0; s < 32; s++)
    P2[s] = __floats2bfloat162_rn(d_P[c * 64 + 2 * s], d_P[c * 64 + 2 * s + 1]);

  // duration weights Λ_d = 2^len_d : scalars d=1,11; pairs (Λ_i, Λ_{i+10}) i=2..10
  const __nv_bfloat16 L1b = __float2bfloat16(ex2(d_lentab[0 * 64 + c]));
  const __nv_bfloat16 L11b = __float2bfloat16(ex2(d_lentab[10 * 64 + c]));
  __nv_bfloat162 L2[11];
#pragma unroll
  for (int i = 2; i <= 10; i++)
    L2[i] = __floats2bfloat162_rn(ex2(d_lentab[(i - 1) * 64 + c]),
                                  ex2(d_lentab[(i + 9) * 64 + c]));

  // ring: at phase P, pair i (=2..10) lives at WP[i+3-P]; fresh pair at WP[4-P]
  __nv_bfloat162 WP[14];
  const __nv_bfloat162 z2 = __float2bfloat162_rn(0.f);
#pragma unroll
  for (int i = 0; i < 14; i++) WP[i] = z2;
  __nv_bfloat16 accb = __float2bfloat16(ex2(d_initlp[c]));   // W1 entering step 1
  __nv_bfloat16 W11b = __float2bfloat16(0.f);

  const int len_b = lengths[b];
  const float* em = d_emission + b * (N_ * C_);
  float emr_a = em[c];            // row 0 = em_1[c]
  float emr_b = em[64 + c];       // row 1
  float emr_c2 = em[128 + c];     // row 2

  float m = em[0] + d_initlp[0] + d_lentab[0];   // exact alpha_1[0] (log2)
  float m_prev = 0.f;
  float beta0_prev = d_initlp[0];

  __nv_bfloat16 my_e = __float2bfloat16(0.f);
  float m_save = 0.f;

#define STEP(P)                                                                  \
  {                                                                              \
    const int t = tb + (P) + 1;                                                  \
    const int BUF = t & 1;                                                       \
    int rpre = (t + 2 < N_) ? (t + 2) : (N_ - 1);   /* IMNMX, branchless */      \
    float emNew = em[rpre * 64 + c];                                             \
    float dm = m - m_prev;                                                       \
    float scf = ex2(emr_a - dm);     /* off-chain: inputs ready early */         \
    __nv_bfloat16 scb = __float2bfloat16(scf);                                   \
    __nv_bfloat162 sc2 = __bfloat162bfloat162(scb);                              \
    __nv_bfloat16 Lsc = __hmul(L1b, scb);                                        \
    /* old-only partial dot (d=2..10,12..20 pairs; d=11 scalar) */               \
    __nv_bfloat162 ha = __hmul2(WP[5 - (P)], L2[2]);                             \
    __nv_bfloat162 hb = __hmul2(WP[6 - (P)], L2[3]);                             \
    ha = __hfma2(WP[7 - (P)], L2[4], ha);                                        \
    hb = __hfma2(WP[8 - (P)], L2[5], hb);                                        \
    ha = __hfma2(WP[9 - (P)], L2[6], ha);                                        \
    hb = __hfma2(WP[10 - (P)], L2[7], hb);                                       \
    ha = __hfma2(WP[11 - (P)], L2[8], ha);                                       \
    hb = __hfma2(WP[12 - (P)], L2[9], hb);                                       \
    ha = __hfma2(WP[13 - (P)], L2[10], ha);                                      \
    ha = __hadd2(ha, hb);                                                        \
    __nv_bfloat16 pb = __hadd(__low2bfloat16(ha), __high2bfloat16(ha));          \
    pb = __hfma(W11b, L11b, pb);                                                 \
    __nv_bfloat16 peb = __hmul(pb, scb);                                         \
    /* aging d10->d11, fresh pair (d2,d12), rescale olds */                      \
    __nv_bfloat16 W11n = __hmul(__low2bfloat16(WP[13 - (P)]), scb);              \
    WP[4 - (P)] = __hmul2(__halves2bfloat162(accb, W11b), sc2);                  \
    _Pragma("unroll")                                                            \
    for (int i = 2; i <= 10; i++)                                                \
      WP[i + 3 - (P)] = __hmul2(WP[i + 3 - (P)], sc2);                           \
    /* e_t = acc*Λ1*sc + pe : pure bf16, no cvt on chain */                      \
    __nv_bfloat16 eb = __hfma(accb, Lsc, peb);                                   \
    e_sm[BUF][c] = eb;                                                           \
    float mval = beta0_prev + emr_a + emr_b;                                     \
    if (c == 0) m_sm[BUF] = mval;                                                \
    __syncthreads();                                                             \
    /* matvec: 8 broadcast LDS.128, 8 HFMA2 chains */                            \
    const uint4* Ev = (const uint4*)&e_sm[BUF][0];                               \
    uint4 u0 = Ev[0], u1 = Ev[1], u2 = Ev[2], u3 = Ev[3];                        \
    const __nv_bfloat162* e0 = (const __nv_bfloat162*)&u0;                       \
    const __nv_bfloat162* e1 = (const __nv_bfloat162*)&u1;                       \
    const __nv_bfloat162* e2p = (const __nv_bfloat162*)&u2;                      \
    const __nv_bfloat162* e3 = (const __nv_bfloat162*)&u3;                       \
    __nv_bfloat162 a0 = __hmul2(P2[0], e0[0]);                                   \
    __nv_bfloat162 a1 = __hmul2(P2[1], e0[1]);                                   \
    __nv_bfloat162 a2 = __hmul2(P2[2], e0[2]);                                   \
    __nv_bfloat162 a3 = __hmul2(P2[3], e0[3]);                                   \
    __nv_bfloat162 a4 = __hmul2(P2[4], e1[0]);                                   \
    __nv_bfloat162 a5 = __hmul2(P2[5], e1[1]);                                   \
    __nv_bfloat162 a6 = __hmul2(P2[6], e1[2]);                                   \
    __nv_bfloat162 a7 = __hmul2(P2[7], e1[3]);                                   \
    a0 = __hfma2(P2[8], e2p[0], a0);                                             \
    a1 = __hfma2(P2[9], e2p[1], a1);                                             \
    a2 = __hfma2(P2[10], e2p[2], a2);                                            \
    a3 = __hfma2(P2[11], e2p[3], a3);                                            \
    a4 = __hfma2(P2[12], e3[0], a4);                                             \
    a5 = __hfma2(P2[13], e3[1], a5);                                             \
    a6 = __hfma2(P2[14], e3[2], a6);                                             \
    a7 = __hfma2(P2[15], e3[3], a7);                                             \
    uint4 v0 = Ev[4], v1 = Ev[5], v2 = Ev[6], v3 = Ev[7];                        \
    const __nv_bfloat162* f0p = (const __nv_bfloat162*)&v0;                      \
    const __nv_bfloat162* f1p = (const __nv_bfloat162*)&v1;                      \
    const __nv_bfloat162* f2p = (const __nv_bfloat162*)&v2;                      \
    const __nv_bfloat162* f3p = (const __nv_bfloat162*)&v3;                      \
    a0 = __hfma2(P2[16], f0p[0], a0);                                            \
    a1 = __hfma2(P2[17], f0p[1], a1);                                            \
    a2 = __hfma2(P2[18], f0p[2], a2);                                            \
    a3 = __hfma2(P2[19], f0p[3], a3);                                            \
    a4 = __hfma2(P2[20], f1p[0], a4);                                            \
    a5 = __hfma2(P2[21], f1p[1], a5);                                            \
    a6 = __hfma2(P2[22], f1p[2], a6);                                            \
    a7 = __hfma2(P2[23], f1p[3], a7);                                            \
    a0 = __hfma2(P2[24], f2p[0], a0);                                            \
    a1 = __hfma2(P2[25], f2p[1], a1);                                            \
    a2 = __hfma2(P2[26], f2p[2], a2);                                            \
    a3 = __hfma2(P2[27], f2p[3], a3);                                            \
    a4 = __hfma2(P2[28], f3p[0], a4);                                            \
    a5 = __hfma2(P2[29], f3p[1], a5);                                            \
    a6 = __hfma2(P2[30], f3p[2], a6);                                            \
    a7 = __hfma2(P2[31], f3p[3], a7);                                            \
    a0 = __hadd2(a0, a1); a2 = __hadd2(a2, a3);                                  \
    a4 = __hadd2(a4, a5); a6 = __hadd2(a6, a7);                                  \
    a0 = __hadd2(a0, a2); a4 = __hadd2(a4, a6);                                  \
    a0 = __hadd2(a0, a4);                                                        \
    __nv_bfloat16 nacc = __hadd(__low2bfloat16(a0), __high2bfloat16(a0));        \
    float accf = __bfloat162float(nacc);     /* off-chain consumers only */      \
    float m_read = m_sm[BUF];                                                    \
    beta0_prev = m + lg2(fmaxf(accf, 1e-30f));                                   \
    bool hit = (t == len_b);                                                     \
    my_e = hit ? eb : my_e;                                                      \
    m_save = hit ? m : m_save;                                                   \
    W11b = W11n; accb = nacc;                                                    \
    m_prev = m; m = m_read;                                                      \
    emr_a = emr_b; emr_b = emr_c2; emr_c2 = emNew;                               \
  }

  for (int tb = 0; tb < N_; tb += 4) {
    STEP(0)
    STEP(1)
    STEP(2)
    STEP(3)
    // restore group invariant: ring index rotation by 4
#pragma unroll
    for (int i = 13; i >= 5; i--) WP[i] = WP[i - 4];
  }
#undef STEP

  // final logZ = m_save + log2(sum_c e_c(len)) (then to nat-log)
  float ef = __bfloat162float(my_e);
#pragma unroll
  for (int o = 16; o > 0; o >>= 1) ef += __shfl_xor_sync(0xffffffffu, ef, o);
  if ((c & 31) == 0) red_sm[c >> 5] = ef;
  __syncthreads();
  if (c == 0) out[b] = (m_save + lg2(red_sm[0] + red_sm[1])) * LN2F;
}

// ---------------------------------------------------------------------------
extern "C" void kernel_launch(void* const* d_in, const int* in_sizes, int n_in,
                              void* d_out, int out_size) {
  const float* feat    = (const float*)d_in[0];
  const int*   lengths = (const int*)d_in[1];
  const float* means   = (const float*)d_in[2];
  const float* cov     = (const float*)d_in[3];
  const float* tl      = (const float*)d_in[4];
  const float* il      = (const float*)d_in[5];
  const float* plr     = (const float*)d_in[6];
  float* out = (float*)d_out;

  prep_kernel<<<1, 256>>>(means, cov, tl, il, plr);
  transpose_kernel<<<dim3(16, 2), 256>>>(means, cov);
  emission_kernel<<<(B_ * N_) / 128, 256>>>(feat);
  scan_kernel<<<B_, 64>>>(lengths, out);
}